// round 6
// baseline (speedup 1.0000x reference)
#include <cuda_runtime.h>
#include <cuda_bf16.h>
#include <cstdint>

#define BATCH 32
#define NA 8400
#define NJ 100
#define NC 80
#define KTOP 13
#define EPSV 1e-9f
#define CAND_CAP 512          // max in-box anchors per GT (<=128px box => ~336 expected)
#define NBY 32                // y-bins of 20px over [0,640)
#define INVBW (32.0f / 640.0f)
#define NBLOCKS 592           // 148 SMs * 4 blocks, guaranteed co-resident
#define NTHREADS 256
#define NTASKS (BATCH * NJ)

// ---------------- device scratch ----------------
__device__ int           g_cnt[BATCH * NA];
__device__ int           g_minj[BATCH * NA];
__device__ float         g_alignsel[BATCH * NA];
__device__ float         g_sel_iou[BATCH * NA];
__device__ int           g_gt[BATCH * NA];
__device__ unsigned char g_pos[BATCH * NA];
__device__ unsigned int  g_posalign[BATCH * NJ];
__device__ unsigned int  g_posovl[BATCH * NJ];
__device__ int           g_bincnt[NBY];
__device__ int           g_binoff[NBY + 1];
__device__ int           g_bincur[NBY];
__device__ int           g_bin_a[NA];
__device__ float2        g_bin_xy[NA];
// software grid barrier
__device__ int           g_bar_cnt;
__device__ volatile int  g_bar_gen;

__device__ __forceinline__ float iou_box(float gx1, float gy1, float gx2, float gy2,
                                         float4 p, float garea) {
    float ix1 = fmaxf(gx1, p.x), iy1 = fmaxf(gy1, p.y);
    float ix2 = fminf(gx2, p.z), iy2 = fminf(gy2, p.w);
    float iw = fmaxf(ix2 - ix1, 0.0f), ih = fmaxf(iy2 - iy1, 0.0f);
    float inter = iw * ih;
    float parea = (p.z - p.x) * (p.w - p.y);
    return inter / (garea + parea - inter + EPSV);
}

__device__ __forceinline__ int ybin(float y) {
    int v = (int)(y * INVBW);
    return max(0, min(NBY - 1, v));
}

__device__ __forceinline__ void grid_barrier() {
    __threadfence();           // release: make my global writes visible
    __syncthreads();           // all threads of block fenced
    if (threadIdx.x == 0) {
        int gen = g_bar_gen;
        if (atomicAdd(&g_bar_cnt, 1) == NBLOCKS - 1) {
            g_bar_cnt = 0;
            __threadfence();
            g_bar_gen = gen + 1;
        } else {
            while (g_bar_gen == gen) __nanosleep(64);
        }
        __threadfence();       // acquire
    }
    __syncthreads();
}

// ==================== the single persistent kernel ====================
__global__ __launch_bounds__(NTHREADS, 4) void k_all(
    const float* __restrict__ ps,    // pred_scores [b,a,c]
    const float* __restrict__ pb,    // pred_bboxes [b,a,4]
    const float* __restrict__ ap,    // anchor_points [a,2]
    const int*   __restrict__ glab,  // gt_labels [b,j]
    const float* __restrict__ gbb,   // gt_bboxes [b,j,4]
    const float* __restrict__ mgt,   // mask_gt [b,j]
    float* __restrict__ out)
{
    __shared__ unsigned long long s_cand[CAND_CAP];
    __shared__ float s_iou[CAND_CAP];
    __shared__ int s_n;

    const int tid  = threadIdx.x;
    const int gtid = blockIdx.x * NTHREADS + tid;
    const int NT   = NBLOCKS * NTHREADS;
    const int lane = tid & 31;

    // ---- phase 0: clear scratch ----
    for (int i = gtid; i < BATCH * NA; i += NT) { g_cnt[i] = 0; g_minj[i] = 0x7FFFFFFF; }
    for (int i = gtid; i < BATCH * NJ; i += NT) { g_posalign[i] = 0u; g_posovl[i] = 0u; }
    if (gtid < NBY) g_bincnt[gtid] = 0;
    grid_barrier();

    // ---- phase 1: y-bin counts ----
    for (int a = gtid; a < NA; a += NT) {
        float2 apt = ((const float2*)ap)[a];
        atomicAdd(&g_bincnt[ybin(apt.y)], 1);
    }
    grid_barrier();

    // ---- phase 2: exclusive scan (block 0, warp 0) ----
    if (blockIdx.x == 0 && tid < NBY) {
        int v = g_bincnt[tid];
        int incl = v;
        #pragma unroll
        for (int off = 1; off < NBY; off <<= 1) {
            int o = __shfl_up_sync(0xFFFFFFFFu, incl, off);
            if (tid >= off) incl += o;
        }
        g_binoff[tid + 1] = incl;
        g_bincur[tid] = incl - v;
        if (tid == 0) g_binoff[0] = 0;
    }
    grid_barrier();

    // ---- phase 3: scatter anchors into y-sorted order ----
    for (int a = gtid; a < NA; a += NT) {
        float2 apt = ((const float2*)ap)[a];
        int pos = atomicAdd(&g_bincur[ybin(apt.y)], 1);
        g_bin_a[pos] = a;
        g_bin_xy[pos] = apt;
    }
    grid_barrier();

    // ---- phase 4: per-(b,j) candidates + exact top-13 ----
    for (int t = blockIdx.x; t < NTASKS; t += NBLOCKS) {
        int b = t & (BATCH - 1);
        int j = t >> 5;
        if (tid == 0) s_n = 0;
        bool valid = (mgt[b * NJ + j] > 0.0f);
        const float4 gb4 = ((const float4*)gbb)[b * NJ + j];
        const float gx1 = gb4.x, gy1 = gb4.y, gx2 = gb4.z, gy2 = gb4.w;
        __syncthreads();

        if (valid) {
            const float garea = (gx2 - gx1) * (gy2 - gy1);
            const int lab = glab[b * NJ + j];
            int cs = g_binoff[ybin(gy1)];
            int ce = g_binoff[ybin(gy2) + 1];
            for (int c = cs + tid; c < ce; c += NTHREADS) {
                float2 apt = g_bin_xy[c];
                float m = fminf(fminf(apt.x - gx1, apt.y - gy1),
                                fminf(gx2 - apt.x, gy2 - apt.y));
                if (m > EPSV) {
                    int a = g_bin_a[c];
                    float4 p = ((const float4*)pb)[(size_t)b * NA + a];
                    float iou = iou_box(gx1, gy1, gx2, gy2, p, garea);
                    float sc = ps[((size_t)b * NA + a) * NC + lab];
                    float i2 = iou * iou;
                    float al = sc * (i2 * i2 * i2);      // score * iou^6
                    int slot = atomicAdd(&s_n, 1);
                    if (slot < CAND_CAP) {
                        s_cand[slot] = ((unsigned long long)__float_as_uint(al) << 32)
                                     | (unsigned)(~a);
                        s_iou[slot] = iou;
                    }
                }
            }
        }
        __syncthreads();

        if (valid && tid < 32) {
            int n = min(s_n, CAND_CAP);
            const int gbase = b * NA;
            for (int it = 0; it < KTOP && it < n; ++it) {
                unsigned long long bv = 0ULL; int bs = -1;
                for (int c = lane; c < n; c += 32) {
                    unsigned long long v = s_cand[c];
                    if (v > bv) { bv = v; bs = c; }
                }
                #pragma unroll
                for (int off = 16; off; off >>= 1) {
                    unsigned long long ov = __shfl_xor_sync(0xFFFFFFFFu, bv, off);
                    int os = __shfl_xor_sync(0xFFFFFFFFu, bs, off);
                    if (ov > bv) { bv = ov; bs = os; }
                }
                if ((unsigned)(bv >> 32) == 0u) break;   // only zeros remain
                if (lane == 0) {
                    int a = (int)(~(unsigned)bv);
                    atomicAdd(&g_cnt[gbase + a], 1);
                    atomicMin(&g_minj[gbase + a], j);
                    g_alignsel[gbase + a] = __uint_as_float((unsigned)(bv >> 32));
                    g_sel_iou[gbase + a]  = s_iou[bs];
                    s_cand[bs] = 0ULL;
                }
                __syncwarp();
            }
        }
        __syncthreads();
    }
    grid_barrier();

    // ---- phase 5: per-anchor resolution (warp-cooperative for multi-claim) ----
    {
        const int total = BATCH * NA;
        const int iters = (total + NT - 1) / NT;
        for (int k = 0; k < iters; ++k) {
            int i = gtid + k * NT;
            bool act = i < total;
            int s = act ? g_cnt[i] : 0;
            if (act) {
                bool pos = s > 0;
                g_pos[i] = pos ? 1 : 0;
                if (!pos) g_gt[i] = 0;
                if (s == 1) {
                    int b = i / NA;
                    int g = g_minj[i];
                    g_gt[i] = g;
                    atomicMax(&g_posalign[b * NJ + g], __float_as_uint(g_alignsel[i]));
                    atomicMax(&g_posovl[b * NJ + g], __float_as_uint(g_sel_iou[i]));
                }
            }
            unsigned mm = __ballot_sync(0xFFFFFFFFu, act && s > 1);
            while (mm) {
                int l = __ffs(mm) - 1; mm &= mm - 1;
                int ii = __shfl_sync(0xFFFFFFFFu, i, l);
                int b = ii / NA;
                float4 p = ((const float4*)pb)[ii];
                unsigned long long bv = 0ULL;
                for (int j = lane; j < NJ; j += 32) {
                    float4 g4 = ((const float4*)gbb)[b * NJ + j];
                    float v = iou_box(g4.x, g4.y, g4.z, g4.w, p,
                                      (g4.z - g4.x) * (g4.w - g4.y));
                    unsigned long long key = ((unsigned long long)__float_as_uint(v) << 32)
                                           | (unsigned)(~j);
                    bv = max(bv, key);
                }
                #pragma unroll
                for (int off = 16; off; off >>= 1)
                    bv = max(bv, __shfl_xor_sync(0xFFFFFFFFu, bv, off));
                if (lane == 0) {
                    int g = (int)(~(unsigned)bv);
                    float iou = __uint_as_float((unsigned)(bv >> 32));
                    int lab = glab[b * NJ + g];
                    float sc = ps[(size_t)ii * NC + lab];
                    float i2 = iou * iou;
                    float al = sc * (i2 * i2 * i2);
                    g_gt[ii] = g;
                    g_alignsel[ii] = al;
                    atomicMax(&g_posalign[b * NJ + g], __float_as_uint(al));
                    atomicMax(&g_posovl[b * NJ + g], __float_as_uint(iou));
                }
            }
        }
    }
    grid_barrier();

    // ---- phase 6: finalization (labels | bboxes | scores | pos) ----
    for (int i = gtid; i < BATCH * NA; i += NT) {
        int b = i / NA;
        bool pos = g_pos[i] != 0;
        int g = g_gt[i];
        float norm = 0.0f; int lab = NC;
        if (pos) {
            int r = b * NJ + g;
            float pa = __uint_as_float(g_posalign[r]);
            float po = __uint_as_float(g_posovl[r]);
            norm = g_alignsel[i] * po / (pa + EPSV);
            lab = glab[r];
        }
        out[i] = (float)lab;
        ((float4*)(out + BATCH * NA))[i] = ((const float4*)gbb)[b * NJ + g];
        out[(size_t)BATCH * NA * 85 + i] = pos ? 1.0f : 0.0f;

        float4* sc = (float4*)(out + (size_t)BATCH * NA * 5 + (size_t)i * NC);
        int lq = lab >> 2, lr = lab & 3;
        #pragma unroll
        for (int q = 0; q < NC / 4; ++q) {
            float4 v = make_float4(0.f, 0.f, 0.f, 0.f);
            if (q == lq) ((float*)&v)[lr] = norm;   // lab==NC never matches
            sc[q] = v;
        }
    }
}

// ---------------- launch ----------------
extern "C" void kernel_launch(void* const* d_in, const int* in_sizes, int n_in,
                              void* d_out, int out_size) {
    const float* pred_scores  = (const float*)d_in[0];
    const float* pred_bboxes  = (const float*)d_in[1];
    const float* anchor_pts   = (const float*)d_in[2];
    const int*   gt_labels    = (const int*)d_in[3];
    const float* gt_bboxes    = (const float*)d_in[4];
    const float* mask_gt      = (const float*)d_in[5];
    float* out = (float*)d_out;

    k_all<<<NBLOCKS, NTHREADS>>>(pred_scores, pred_bboxes, anchor_pts,
                                 gt_labels, gt_bboxes, mask_gt, out);
}